// round 9
// baseline (speedup 1.0000x reference)
#include <cuda_runtime.h>
#include <cuda_bf16.h>
#include <math.h>
#include <stdint.h>

#define TT 512
#define BB 64
#define DD 1024
#define HH 1024
#define GG 4096
#define NCTA 128

// ---------------------------------------------------------------------------
// Device scratch (allocation-free rules: __device__ globals)
// ---------------------------------------------------------------------------
static __device__ float g_gx[(size_t)TT * BB * GG];            // input gates (+biases)
static __device__ __nv_bfloat16 g_xhi[(size_t)TT * BB * DD];   // x split
static __device__ __nv_bfloat16 g_xlo[(size_t)TT * BB * DD];
static __device__ __nv_bfloat16 g_wihhi[GG * DD];              // w_ih split
static __device__ __nv_bfloat16 g_wihlo[GG * DD];
static __device__ __nv_bfloat16 g_whhhi[GG * HH];              // w_hh split, CTA-tiled rows
static __device__ __nv_bfloat16 g_whhlo[GG * HH];
static __device__ __nv_bfloat16 g_hhi[2][BB * HH];             // h split ping-pong
static __device__ __nv_bfloat16 g_hlo[2][BB * HH];
static __device__ unsigned g_flag[NCTA];                       // per-CTA step flags (monotonic)

// ---------------------------------------------------------------------------
// Baseline-PTX tensor helpers (sm_80+: compile for plain sm_103)
// ---------------------------------------------------------------------------
__device__ __forceinline__ uint32_t smem_u32(const void* p) {
    uint32_t a;
    asm("{ .reg .u64 t; cvta.to.shared.u64 t, %1; cvt.u32.u64 %0, t; }"
        : "=r"(a) : "l"(p));
    return a;
}
__device__ __forceinline__ void cp16(uint32_t dst, const void* src) {
    asm volatile("cp.async.cg.shared.global [%0], [%1], 16;" :: "r"(dst), "l"(src) : "memory");
}
#define CP_COMMIT() asm volatile("cp.async.commit_group;" ::: "memory")
#define CP_WAIT0()  asm volatile("cp.async.wait_group 0;" ::: "memory")
#define CP_WAIT1()  asm volatile("cp.async.wait_group 1;" ::: "memory")

__device__ __forceinline__ void ldsm4(uint32_t addr, uint32_t* r) {
    asm volatile("ldmatrix.sync.aligned.m8n8.x4.shared.b16 {%0,%1,%2,%3}, [%4];"
                 : "=r"(r[0]), "=r"(r[1]), "=r"(r[2]), "=r"(r[3]) : "r"(addr));
}
__device__ __forceinline__ void mma16816(float* c, const uint32_t* a, const uint32_t* b) {
    asm volatile("mma.sync.aligned.m16n8k16.row.col.f32.bf16.bf16.f32 "
                 "{%0,%1,%2,%3}, {%4,%5,%6,%7}, {%8,%9}, {%0,%1,%2,%3};"
                 : "+f"(c[0]), "+f"(c[1]), "+f"(c[2]), "+f"(c[3])
                 : "r"(a[0]), "r"(a[1]), "r"(a[2]), "r"(a[3]), "r"(b[0]), "r"(b[1]));
}
__device__ __forceinline__ unsigned flag_acq(const unsigned* p) {
    unsigned v;
    asm volatile("ld.acquire.gpu.global.u32 %0, [%1];" : "=r"(v) : "l"(p) : "memory");
    return v;
}
__device__ __forceinline__ void flag_rel(unsigned* p, unsigned v) {
    asm volatile("st.release.gpu.global.u32 [%0], %1;" :: "l"(p), "r"(v) : "memory");
}

// ---------------------------------------------------------------------------
// Prep kernels: fp32 -> bf16 hi/lo splits
// ---------------------------------------------------------------------------
__device__ __forceinline__ void split_bf16(float v, __nv_bfloat16* hi, __nv_bfloat16* lo) {
    __nv_bfloat16 h = __float2bfloat16(v);
    *hi = h;
    *lo = __float2bfloat16(v - __bfloat162float(h));
}
__global__ void prep_x_kernel(const float* __restrict__ x) {
    size_t idx = (size_t)blockIdx.x * blockDim.x + threadIdx.x;
    if (idx >= (size_t)TT * BB * DD) return;
    split_bf16(x[idx], &g_xhi[idx], &g_xlo[idx]);
}
__global__ void prep_wih_kernel(const float* __restrict__ w) {
    int idx = blockIdx.x * blockDim.x + threadIdx.x;
    if (idx >= GG * DD) return;
    split_bf16(w[idx], &g_wihhi[idx], &g_wihlo[idx]);
}
// w_hh reorder: CTA cta owns 32 rows r = g*8+jl  <->  in_row = g*1024 + cta*8 + jl
__global__ void prep_whh_kernel(const float* __restrict__ w) {
    int idx = blockIdx.x * blockDim.x + threadIdx.x;
    if (idx >= GG * HH) return;
    int orow = idx >> 10, k = idx & 1023;
    int cta = orow >> 5, r = orow & 31;
    int g = r >> 3, jl = r & 7;
    int in_row = (g << 10) + (cta << 3) + jl;
    split_bf16(w[(size_t)in_row * HH + k], &g_whhhi[idx], &g_whhlo[idx]);
}
__global__ void prep_h_kernel(const float* __restrict__ h0) {
    int idx = blockIdx.x * blockDim.x + threadIdx.x;
    if (idx >= BB * HH) return;
    split_bf16(h0[idx], &g_hhi[0][idx], &g_hlo[0][idx]);
}

// ---------------------------------------------------------------------------
// Phase 1: gates_x = x @ w_ih^T + b_ih + b_hh  via mma.sync, 3-term split.
// ---------------------------------------------------------------------------
#define P1_STG 10240
#define P1_AHI 0
#define P1_ALO 20480
#define P1_BHI 40960
#define P1_BLO 61440
#define P1_SMEM 81920

__global__ __launch_bounds__(256, 2) void gemm_gx_mma(
    const float* __restrict__ bih, const float* __restrict__ bhh)
{
    extern __shared__ __align__(16) char sm[];
    const uint32_t sb = smem_u32(sm);
    const int tid = threadIdx.x;
    const int wid = tid >> 5, l = tid & 31;
    const int bm = blockIdx.y * 128, bn = blockIdx.x * 128;
    const int wm = wid & 3, wn = wid >> 2;

    const int a_r = wm * 32 + (l & 7) + ((l >> 3) & 1) * 8;
    const int a_cb = ((l >> 4) & 1) * 8;
    const int b_r = wn * 64 + (l & 7) + ((l >> 4) & 1) * 8;
    const int b_cb = ((l >> 3) & 1) * 8;

    float acc[2][8][4];
#pragma unroll
    for (int i = 0; i < 2; i++)
#pragma unroll
        for (int j = 0; j < 8; j++)
#pragma unroll
            for (int q = 0; q < 4; q++) acc[i][j][q] = 0.f;

    const int crow = tid >> 2, cseg = tid & 3;
    auto load_stage = [&](int c, int st) {
        const uint32_t so = st * P1_STG;
        size_t koff = (size_t)c * 32 + cseg * 8;
#pragma unroll
        for (int i = 0; i < 2; i++) {
            int row = crow + i * 64;
            uint32_t sofs = (uint32_t)(row * 80 + cseg * 16);
            cp16(sb + P1_AHI + so + sofs, g_xhi + (size_t)(bm + row) * DD + koff);
            cp16(sb + P1_ALO + so + sofs, g_xlo + (size_t)(bm + row) * DD + koff);
            cp16(sb + P1_BHI + so + sofs, g_wihhi + (size_t)(bn + row) * DD + koff);
            cp16(sb + P1_BLO + so + sofs, g_wihlo + (size_t)(bn + row) * DD + koff);
        }
        CP_COMMIT();
    };

    load_stage(0, 0);

    for (int c = 0; c < 32; c++) {
        if (c < 31) load_stage(c + 1, (c + 1) & 1);
        if (c < 31) { CP_WAIT1(); } else { CP_WAIT0(); }
        __syncthreads();
        const uint32_t so = (c & 1) * P1_STG;
#pragma unroll
        for (int kb = 0; kb < 32; kb += 16) {
            uint32_t ahi[2][4], alo[2][4];
#pragma unroll
            for (int am = 0; am < 2; am++) {
                uint32_t aofs = (uint32_t)((a_r + am * 16) * 80 + (kb + a_cb) * 2);
                ldsm4(sb + P1_AHI + so + aofs, ahi[am]);
                ldsm4(sb + P1_ALO + so + aofs, alo[am]);
            }
#pragma unroll
            for (int bg = 0; bg < 4; bg++) {
                uint32_t bh[4], bl[4];
                uint32_t bofs = (uint32_t)((b_r + bg * 16) * 80 + (kb + b_cb) * 2);
                ldsm4(sb + P1_BHI + so + bofs, bh);
                ldsm4(sb + P1_BLO + so + bofs, bl);
#pragma unroll
                for (int am = 0; am < 2; am++)
#pragma unroll
                    for (int na = 0; na < 2; na++) {
                        float* cc = acc[am][bg * 2 + na];
                        mma16816(cc, ahi[am], bh + na * 2);
                        mma16816(cc, alo[am], bh + na * 2);
                        mma16816(cc, ahi[am], bl + na * 2);
                    }
            }
        }
        __syncthreads();
    }

#pragma unroll
    for (int am = 0; am < 2; am++) {
        int m0 = bm + wm * 32 + am * 16 + (l >> 2);
#pragma unroll
        for (int j = 0; j < 8; j++) {
            int n = bn + wn * 64 + j * 8 + 2 * (l & 3);
            float s0 = bih[n] + bhh[n];
            float s1 = bih[n + 1] + bhh[n + 1];
            float* c = acc[am][j];
            g_gx[(size_t)m0 * GG + n]           = c[0] + s0;
            g_gx[(size_t)m0 * GG + n + 1]       = c[1] + s1;
            g_gx[(size_t)(m0 + 8) * GG + n]     = c[2] + s0;
            g_gx[(size_t)(m0 + 8) * GG + n + 1] = c[3] + s1;
        }
    }
}

// ---------------------------------------------------------------------------
// Phase 2: persistent mma.sync recurrence with dataflow (flag) sync.
// 128 CTAs x 512 threads. CTA: D[64 batch x 32 gate-rows], K=1024,
// 8 chunks of 128 consumed in rotated order starting at own chunk group.
// Producer CTA flags its 8 h-columns; consumers wait per-chunk on the 16
// producer flags of that chunk, with acquire-peek issued one chunk ahead.
// ---------------------------------------------------------------------------
#define R_SWHI 0            // 32 x 2064B = 66048
#define R_SWLO 66048
#define R_SH   132096       // 2 stages x 34816 (hi 17408 + lo 17408)
#define R_HSTG 34816
#define R_SMEM 201728
// sg (2 planes x 64 x 36 floats = 18432 B) aliases h-stage 0

__global__ __launch_bounds__(512, 1) void lstm_mma_kernel(
    const float* __restrict__ c0, float* __restrict__ out)
{
    extern __shared__ __align__(16) char sm[];
    const uint32_t sb = smem_u32(sm);
    float* sg = (float*)(sm + R_SH);
    const int tid = threadIdx.x;
    const int wid = tid >> 5, l = tid & 31;
    const int j0 = blockIdx.x * 8;
    const int cg = blockIdx.x >> 4;       // own chunk group (columns j0 live in chunk cg)

    // replay-safe base: all slots equal between runs; read before any producer
    // of this run can increment (co-resident wave-1, producers flag only after
    // a full step ~10us later).
    const unsigned base = *(volatile unsigned*)&g_flag[blockIdx.x];

    const __nv_bfloat16* whi = g_whhhi + (size_t)blockIdx.x * 32 * HH;
    const __nv_bfloat16* wlo = g_whhlo + (size_t)blockIdx.x * 32 * HH;

    // ---- Load W (hi+lo) into SMEM once ----
    for (int cid = tid; cid < 4096; cid += 512) {
        int row = cid >> 7, seg = cid & 127;
        uint32_t sofs = (uint32_t)(row * 2064 + seg * 16);
        *(uint4*)(sm + R_SWHI + sofs) = *(const uint4*)(whi + (size_t)row * HH + seg * 8);
        *(uint4*)(sm + R_SWLO + sofs) = *(const uint4*)(wlo + (size_t)row * HH + seg * 8);
    }

    // cell state: 1 elem/thread
    const int pb = tid >> 3, pjl = tid & 7;
    float c_reg = c0[(size_t)pb * HH + j0 + pjl];
    __syncthreads();

    // warp geometry: kh = K-half, w8 in 4m x 2n
    const int kh = wid >> 3, w8 = wid & 7;
    const int m0 = (w8 & 3) * 16, n0 = (w8 >> 2) * 16;
    const int a_r = m0 + (l & 7) + ((l >> 3) & 1) * 8;
    const int a_cb = ((l >> 4) & 1) * 8;
    const int b_r = n0 + (l & 7) + ((l >> 4) & 1) * 8;
    const int b_cb = ((l >> 3) & 1) * 8;

    const int hrow = tid >> 3, hseg = tid & 7;

    // flag helpers (lanes 0..15 of every warp check the 16 producers of a group)
    auto peek = [&](int grp) -> unsigned {
        return (l < 16) ? flag_acq(&g_flag[grp * 16 + l]) : 0u;
    };
    auto ready = [&](unsigned v, unsigned tgt) -> bool {
        bool mine = (l >= 16) || ((int)(v - tgt) >= 0);
        return __all_sync(0xFFFFFFFFu, mine);
    };

    // initial gx prefetch (t = 0)
    float gpre[4];
    {
        const float* gr = g_gx + (size_t)pb * GG + j0 + pjl;
#pragma unroll
        for (int g = 0; g < 4; g++) gpre[g] = gr[g * HH];
    }

    for (int t = 0; t < TT; t++) {
        const __nv_bfloat16* hhi = g_hhi[t & 1];
        const __nv_bfloat16* hlo = g_hlo[t & 1];
        const unsigned target = base + (unsigned)t;

        float acc[2][4];
#pragma unroll
        for (int na = 0; na < 2; na++)
#pragma unroll
            for (int q = 0; q < 4; q++) acc[na][q] = 0.f;

        auto load_h = [&](int c, int st) {
            const uint32_t so = R_SH + st * R_HSTG;
            const size_t base2 = (size_t)hrow * HH + c * 128;
#pragma unroll
            for (int i = 0; i < 2; i++) {
                int seg = hseg + i * 8;
                uint32_t sofs = (uint32_t)(hrow * 272 + seg * 16);
                cp16(sb + so + sofs,         hhi + base2 + seg * 8);
                cp16(sb + so + 17408 + sofs, hlo + base2 + seg * 8);
            }
            CP_COMMIT();
        };

        // wait own group (self + 15 neighbors), load first chunk
        {
            unsigned pv = peek(cg);
            while (!ready(pv, target)) pv = peek(cg);
        }
        load_h(cg, 0);
        unsigned pv1 = peek((cg + 1) & 7);   // peek chunk idx[1]

        for (int i = 0; i < 8; i++) {
            const int cur = (cg + i) & 7;
            if (i < 7) {
                const int nxt = (cg + i + 1) & 7;
                while (!ready(pv1, target)) pv1 = peek(nxt);
                load_h(nxt, (i + 1) & 1);
                if (i < 6) pv1 = peek((cg + i + 2) & 7);
            }
            if (i < 7) { CP_WAIT1(); } else { CP_WAIT0(); }
            __syncthreads();
            const uint32_t so = R_SH + (i & 1) * R_HSTG;
#pragma unroll
            for (int kk = 0; kk < 64; kk += 16) {
                const int kb = kh * 64 + kk;
                uint32_t ahi[4], alo[4], bh[4], bl[4];
                uint32_t aofs = (uint32_t)(a_r * 272 + (kb + a_cb) * 2);
                ldsm4(sb + so + aofs, ahi);
                ldsm4(sb + so + 17408 + aofs, alo);
                uint32_t bofs = (uint32_t)(b_r * 2064 + (cur * 128 + kb + b_cb) * 2);
                ldsm4(sb + R_SWHI + bofs, bh);
                ldsm4(sb + R_SWLO + bofs, bl);
#pragma unroll
                for (int na = 0; na < 2; na++) {
                    mma16816(acc[na], ahi, bh + na * 2);
                    mma16816(acc[na], alo, bh + na * 2);
                    mma16816(acc[na], ahi, bl + na * 2);
                }
            }
            __syncthreads();
        }

        // prefetch next step's gx (hides DRAM latency under epilogue)
        float gnext[4];
        if (t < TT - 1) {
            const float* gr = g_gx + (size_t)(t + 1) * BB * GG
                              + (size_t)pb * GG + j0 + pjl;
#pragma unroll
            for (int g = 0; g < 4; g++) gnext[g] = gr[g * HH];
        }

        // stage partial D planes to SMEM (plane kh)
        {
            float* sgp = sg + kh * (64 * 36);
            int m = m0 + (l >> 2);
#pragma unroll
            for (int na = 0; na < 2; na++) {
                int n = n0 + na * 8 + 2 * (l & 3);
                *(float2*)&sgp[m * 36 + n]       = make_float2(acc[na][0], acc[na][1]);
                *(float2*)&sgp[(m + 8) * 36 + n] = make_float2(acc[na][2], acc[na][3]);
            }
        }
        __syncthreads();

        // pointwise LSTM cell: 1 elem/thread
        float* h_out = out + (size_t)t * BB * HH;
        __nv_bfloat16* nhhi = g_hhi[(t + 1) & 1];
        __nv_bfloat16* nhlo = g_hlo[(t + 1) & 1];
        {
            const float* s0 = sg + pb * 36;
            const float* s1 = sg + 64 * 36 + pb * 36;
            float gi = s0[pjl]      + s1[pjl]      + gpre[0];
            float gf = s0[8 + pjl]  + s1[8 + pjl]  + gpre[1];
            float gg = s0[16 + pjl] + s1[16 + pjl] + gpre[2];
            float go = s0[24 + pjl] + s1[24 + pjl] + gpre[3];
            float ig = 1.0f / (1.0f + __expf(-gi));
            float fg = 1.0f / (1.0f + __expf(-gf));
            float gv = tanhf(gg);
            float og = 1.0f / (1.0f + __expf(-go));
            float cn = fg * c_reg + ig * gv;
            float hn = og * tanhf(cn);
            c_reg = cn;
            size_t hoff = (size_t)pb * HH + j0 + pjl;
            h_out[hoff] = hn;
            __nv_bfloat16 hh, hl;
            split_bf16(hn, &hh, &hl);
            nhhi[hoff] = hh;
            nhlo[hoff] = hl;
            if (t == TT - 1) {
                out[(size_t)TT * BB * HH + hoff] = hn;
                out[(size_t)TT * BB * HH + BB * HH + hoff] = cn;
            }
        }
#pragma unroll
        for (int g = 0; g < 4; g++) gpre[g] = gnext[g];

        // publish: all h writes visible, then release own flag
        if (t < TT - 1) {
            __threadfence();
            __syncthreads();
            if (tid == 0) flag_rel(&g_flag[blockIdx.x], base + (unsigned)(t + 1));
        }
    }
}

extern "C" void kernel_launch(void* const* d_in, const int* in_sizes, int n_in,
                              void* d_out, int out_size)
{
    const float* x    = (const float*)d_in[0];
    const float* h0   = (const float*)d_in[1];
    const float* c0   = (const float*)d_in[2];
    const float* w_ih = (const float*)d_in[3];
    const float* b_ih = (const float*)d_in[4];
    const float* w_hh = (const float*)d_in[5];
    const float* b_hh = (const float*)d_in[6];
    float* out = (float*)d_out;
    (void)in_sizes; (void)n_in; (void)out_size;

    // Prep: bf16 hi/lo splits
    prep_x_kernel<<<(int)(((size_t)TT * BB * DD + 255) / 256), 256>>>(x);
    prep_wih_kernel<<<(GG * DD + 255) / 256, 256>>>(w_ih);
    prep_whh_kernel<<<(GG * HH + 255) / 256, 256>>>(w_hh);
    prep_h_kernel<<<(BB * HH + 255) / 256, 256>>>(h0);

    // Phase 1: input projection on tensor cores
    cudaFuncSetAttribute(gemm_gx_mma,
                         cudaFuncAttributeMaxDynamicSharedMemorySize, P1_SMEM);
    dim3 g1(GG / 128, (TT * BB) / 128);
    gemm_gx_mma<<<g1, 256, P1_SMEM>>>(b_ih, b_hh);

    // Phase 2: persistent tensor-core recurrence (dataflow sync)
    cudaFuncSetAttribute(lstm_mma_kernel,
                         cudaFuncAttributeMaxDynamicSharedMemorySize, R_SMEM);
    lstm_mma_kernel<<<NCTA, 512, R_SMEM>>>(c0, out);
}

// round 10
// speedup vs baseline: 2.0153x; 2.0153x over previous
#include <cuda_runtime.h>
#include <cuda_bf16.h>
#include <cuda_fp16.h>
#include <math.h>
#include <stdint.h>

#define TT 512
#define BB 64
#define DD 1024
#define HH 1024
#define GG 4096
#define NCTA 128

// ---------------------------------------------------------------------------
// Device scratch (allocation-free rules: __device__ globals)
// ---------------------------------------------------------------------------
static __device__ float g_gx[(size_t)TT * BB * GG];            // input gates (+biases)
static __device__ __nv_bfloat16 g_xhi[(size_t)TT * BB * DD];   // x split (phase 1)
static __device__ __nv_bfloat16 g_xlo[(size_t)TT * BB * DD];
static __device__ __nv_bfloat16 g_wihhi[GG * DD];              // w_ih split (phase 1)
static __device__ __nv_bfloat16 g_wihlo[GG * DD];
static __device__ __half g_whh16[GG * HH];                     // w_hh fp16, CTA-tiled rows
static __device__ __half g_h16[2][BB * HH];                    // h fp16 ping-pong
static __device__ unsigned g_arrive = 0;
static __device__ unsigned g_release = 0;

// ---------------------------------------------------------------------------
// Baseline-PTX tensor helpers (sm_80+: compile for plain sm_103)
// ---------------------------------------------------------------------------
__device__ __forceinline__ uint32_t smem_u32(const void* p) {
    uint32_t a;
    asm("{ .reg .u64 t; cvta.to.shared.u64 t, %1; cvt.u32.u64 %0, t; }"
        : "=r"(a) : "l"(p));
    return a;
}
__device__ __forceinline__ void cp16(uint32_t dst, const void* src) {
    asm volatile("cp.async.cg.shared.global [%0], [%1], 16;" :: "r"(dst), "l"(src) : "memory");
}
#define CP_COMMIT() asm volatile("cp.async.commit_group;" ::: "memory")
#define CP_WAIT0()  asm volatile("cp.async.wait_group 0;" ::: "memory")
#define CP_WAIT1()  asm volatile("cp.async.wait_group 1;" ::: "memory")
#define CP_WAIT2()  asm volatile("cp.async.wait_group 2;" ::: "memory")
#define CP_WAIT3()  asm volatile("cp.async.wait_group 3;" ::: "memory")

__device__ __forceinline__ void ldsm4(uint32_t addr, uint32_t* r) {
    asm volatile("ldmatrix.sync.aligned.m8n8.x4.shared.b16 {%0,%1,%2,%3}, [%4];"
                 : "=r"(r[0]), "=r"(r[1]), "=r"(r[2]), "=r"(r[3]) : "r"(addr));
}
__device__ __forceinline__ void mma16816bf(float* c, const uint32_t* a, const uint32_t* b) {
    asm volatile("mma.sync.aligned.m16n8k16.row.col.f32.bf16.bf16.f32 "
                 "{%0,%1,%2,%3}, {%4,%5,%6,%7}, {%8,%9}, {%0,%1,%2,%3};"
                 : "+f"(c[0]), "+f"(c[1]), "+f"(c[2]), "+f"(c[3])
                 : "r"(a[0]), "r"(a[1]), "r"(a[2]), "r"(a[3]), "r"(b[0]), "r"(b[1]));
}
__device__ __forceinline__ void mma16816h(float* c, const uint32_t* a, const uint32_t* b) {
    asm volatile("mma.sync.aligned.m16n8k16.row.col.f32.f16.f16.f32 "
                 "{%0,%1,%2,%3}, {%4,%5,%6,%7}, {%8,%9}, {%0,%1,%2,%3};"
                 : "+f"(c[0]), "+f"(c[1]), "+f"(c[2]), "+f"(c[3])
                 : "r"(a[0]), "r"(a[1]), "r"(a[2]), "r"(a[3]), "r"(b[0]), "r"(b[1]));
}

// ---------------------------------------------------------------------------
// Prep kernels
// ---------------------------------------------------------------------------
__device__ __forceinline__ void split_bf16(float v, __nv_bfloat16* hi, __nv_bfloat16* lo) {
    __nv_bfloat16 h = __float2bfloat16(v);
    *hi = h;
    *lo = __float2bfloat16(v - __bfloat162float(h));
}
__global__ void prep_x_kernel(const float* __restrict__ x) {
    size_t idx = (size_t)blockIdx.x * blockDim.x + threadIdx.x;
    if (idx >= (size_t)TT * BB * DD) return;
    split_bf16(x[idx], &g_xhi[idx], &g_xlo[idx]);
}
__global__ void prep_wih_kernel(const float* __restrict__ w) {
    int idx = blockIdx.x * blockDim.x + threadIdx.x;
    if (idx >= GG * DD) return;
    split_bf16(w[idx], &g_wihhi[idx], &g_wihlo[idx]);
}
// w_hh reorder to fp16: CTA cta owns 32 rows r = g*8+jl <-> in_row = g*1024+cta*8+jl
__global__ void prep_whh_kernel(const float* __restrict__ w) {
    int idx = blockIdx.x * blockDim.x + threadIdx.x;
    if (idx >= GG * HH) return;
    int orow = idx >> 10, k = idx & 1023;
    int cta = orow >> 5, r = orow & 31;
    int g = r >> 3, jl = r & 7;
    int in_row = (g << 10) + (cta << 3) + jl;
    g_whh16[idx] = __float2half(w[(size_t)in_row * HH + k]);
}
__global__ void prep_h_kernel(const float* __restrict__ h0) {
    int idx = blockIdx.x * blockDim.x + threadIdx.x;
    if (idx >= BB * HH) return;
    g_h16[0][idx] = __float2half(h0[idx]);
}

// ---------------------------------------------------------------------------
// Phase 1: gates_x = x @ w_ih^T + b_ih + b_hh  via mma.sync bf16 3-term split.
// (unchanged from round 8 — proven, fp32-exact to ~1e-7)
// ---------------------------------------------------------------------------
#define P1_STG 10240
#define P1_AHI 0
#define P1_ALO 20480
#define P1_BHI 40960
#define P1_BLO 61440
#define P1_SMEM 81920

__global__ __launch_bounds__(256, 2) void gemm_gx_mma(
    const float* __restrict__ bih, const float* __restrict__ bhh)
{
    extern __shared__ __align__(16) char sm[];
    const uint32_t sb = smem_u32(sm);
    const int tid = threadIdx.x;
    const int wid = tid >> 5, l = tid & 31;
    const int bm = blockIdx.y * 128, bn = blockIdx.x * 128;
    const int wm = wid & 3, wn = wid >> 2;

    const int a_r = wm * 32 + (l & 7) + ((l >> 3) & 1) * 8;
    const int a_cb = ((l >> 4) & 1) * 8;
    const int b_r = wn * 64 + (l & 7) + ((l >> 4) & 1) * 8;
    const int b_cb = ((l >> 3) & 1) * 8;

    float acc[2][8][4];
#pragma unroll
    for (int i = 0; i < 2; i++)
#pragma unroll
        for (int j = 0; j < 8; j++)
#pragma unroll
            for (int q = 0; q < 4; q++) acc[i][j][q] = 0.f;

    const int crow = tid >> 2, cseg = tid & 3;
    auto load_stage = [&](int c, int st) {
        const uint32_t so = st * P1_STG;
        size_t koff = (size_t)c * 32 + cseg * 8;
#pragma unroll
        for (int i = 0; i < 2; i++) {
            int row = crow + i * 64;
            uint32_t sofs = (uint32_t)(row * 80 + cseg * 16);
            cp16(sb + P1_AHI + so + sofs, g_xhi + (size_t)(bm + row) * DD + koff);
            cp16(sb + P1_ALO + so + sofs, g_xlo + (size_t)(bm + row) * DD + koff);
            cp16(sb + P1_BHI + so + sofs, g_wihhi + (size_t)(bn + row) * DD + koff);
            cp16(sb + P1_BLO + so + sofs, g_wihlo + (size_t)(bn + row) * DD + koff);
        }
        CP_COMMIT();
    };

    load_stage(0, 0);

    for (int c = 0; c < 32; c++) {
        if (c < 31) load_stage(c + 1, (c + 1) & 1);
        if (c < 31) { CP_WAIT1(); } else { CP_WAIT0(); }
        __syncthreads();
        const uint32_t so = (c & 1) * P1_STG;
#pragma unroll
        for (int kb = 0; kb < 32; kb += 16) {
            uint32_t ahi[2][4], alo[2][4];
#pragma unroll
            for (int am = 0; am < 2; am++) {
                uint32_t aofs = (uint32_t)((a_r + am * 16) * 80 + (kb + a_cb) * 2);
                ldsm4(sb + P1_AHI + so + aofs, ahi[am]);
                ldsm4(sb + P1_ALO + so + aofs, alo[am]);
            }
#pragma unroll
            for (int bg = 0; bg < 4; bg++) {
                uint32_t bh[4], bl[4];
                uint32_t bofs = (uint32_t)((b_r + bg * 16) * 80 + (kb + b_cb) * 2);
                ldsm4(sb + P1_BHI + so + bofs, bh);
                ldsm4(sb + P1_BLO + so + bofs, bl);
#pragma unroll
                for (int am = 0; am < 2; am++)
#pragma unroll
                    for (int na = 0; na < 2; na++) {
                        float* cc = acc[am][bg * 2 + na];
                        mma16816bf(cc, ahi[am], bh + na * 2);
                        mma16816bf(cc, alo[am], bh + na * 2);
                        mma16816bf(cc, ahi[am], bl + na * 2);
                    }
            }
        }
        __syncthreads();
    }

#pragma unroll
    for (int am = 0; am < 2; am++) {
        int m0 = bm + wm * 32 + am * 16 + (l >> 2);
#pragma unroll
        for (int j = 0; j < 8; j++) {
            int n = bn + wn * 64 + j * 8 + 2 * (l & 3);
            float s0 = bih[n] + bhh[n];
            float s1 = bih[n + 1] + bhh[n + 1];
            float* c = acc[am][j];
            g_gx[(size_t)m0 * GG + n]           = c[0] + s0;
            g_gx[(size_t)m0 * GG + n + 1]       = c[1] + s1;
            g_gx[(size_t)(m0 + 8) * GG + n]     = c[2] + s0;
            g_gx[(size_t)(m0 + 8) * GG + n + 1] = c[3] + s1;
        }
    }
}

// ---------------------------------------------------------------------------
// Phase 2: persistent fp16 single-term mma.sync recurrence.
// 128 CTAs x 512 threads. CTA: D[64 batch x 32 gate-rows], K=1024,
// 8 chunks of 128 with a 4-stage cp.async pipeline (prefetch depth 3).
// Global barrier per step (round-8 proven variant).
// ---------------------------------------------------------------------------
#define R_SW   0            // 32 rows x 2064B = 66048
#define R_SH   66048        // 4 stages x 17408B = 69632
#define R_HSTG 17408
#define R_SMEM 135680
// sg (2 planes x 64 x 36 floats = 18432 B) aliases h-stage 0 (post-mainloop)

__global__ __launch_bounds__(512, 1) void lstm_mma_kernel(
    const float* __restrict__ c0, float* __restrict__ out)
{
    extern __shared__ __align__(16) char sm[];
    const uint32_t sb = smem_u32(sm);
    float* sg = (float*)(sm + R_SH);
    const int tid = threadIdx.x;
    const int wid = tid >> 5, l = tid & 31;
    const int j0 = blockIdx.x * 8;

    const unsigned rel_base = *(volatile unsigned*)&g_release;

    const __half* w16 = g_whh16 + (size_t)blockIdx.x * 32 * HH;

    // ---- Load W into SMEM once: 32 rows x 1024 fp16, row stride 2064B ----
    for (int cid = tid; cid < 4096; cid += 512) {
        int row = cid >> 7, seg = cid & 127;
        uint32_t sofs = (uint32_t)(row * 2064 + seg * 16);
        *(uint4*)(sm + R_SW + sofs) = *(const uint4*)(w16 + (size_t)row * HH + seg * 8);
    }

    // cell state: 1 elem/thread
    const int pb = tid >> 3, pjl = tid & 7;
    float c_reg = c0[(size_t)pb * HH + j0 + pjl];
    __syncthreads();

    // warp geometry: kh = K-half, w8 in 4m x 2n (warp tile m16 x n16)
    const int kh = wid >> 3, w8 = wid & 7;
    const int m0 = (w8 & 3) * 16, n0 = (w8 >> 2) * 16;
    const int a_r = m0 + (l & 7) + ((l >> 3) & 1) * 8;
    const int a_cb = ((l >> 4) & 1) * 8;
    const int b_r = n0 + (l & 7) + ((l >> 4) & 1) * 8;
    const int b_cb = ((l >> 3) & 1) * 8;

    const int hrow = tid >> 3, hseg = tid & 7;   // 64 rows x 16 segs, 2 per thread

    // initial gx prefetch (t = 0)
    float gpre[4];
    {
        const float* gr = g_gx + (size_t)pb * GG + j0 + pjl;
#pragma unroll
        for (int g = 0; g < 4; g++) gpre[g] = gr[g * HH];
    }

    for (int t = 0; t < TT; t++) {
        const __half* h16 = g_h16[t & 1];

        float acc[2][4];
#pragma unroll
        for (int na = 0; na < 2; na++)
#pragma unroll
            for (int q = 0; q < 4; q++) acc[na][q] = 0.f;

        auto load_h = [&](int c, int st) {
            const uint32_t so = R_SH + st * R_HSTG;
            const size_t base2 = (size_t)hrow * HH + c * 128;
#pragma unroll
            for (int i = 0; i < 2; i++) {
                int seg = hseg + i * 8;
                uint32_t sofs = (uint32_t)(hrow * 272 + seg * 16);
                cp16(sb + so + sofs, h16 + base2 + seg * 8);
            }
            CP_COMMIT();
        };

        // prologue: prefetch chunks 0..2
        load_h(0, 0);
        load_h(1, 1);
        load_h(2, 2);

        for (int c = 0; c < 8; c++) {
            if (c < 5) load_h(c + 3, (c + 3) & 3);
            if (c < 5) { CP_WAIT3(); }
            else if (c == 5) { CP_WAIT2(); }
            else if (c == 6) { CP_WAIT1(); }
            else { CP_WAIT0(); }
            __syncthreads();
            const uint32_t so = R_SH + (c & 3) * R_HSTG;
#pragma unroll
            for (int kk = 0; kk < 64; kk += 16) {
                const int kb = kh * 64 + kk;
                uint32_t ah[4], bh[4];
                uint32_t aofs = (uint32_t)(a_r * 272 + (kb + a_cb) * 2);
                ldsm4(sb + so + aofs, ah);
                uint32_t bofs = (uint32_t)(b_r * 2064 + (c * 128 + kb + b_cb) * 2);
                ldsm4(sb + R_SW + bofs, bh);
#pragma unroll
                for (int na = 0; na < 2; na++)
                    mma16816h(acc[na], ah, bh + na * 2);
            }
            __syncthreads();
        }

        // prefetch next step's gx (hides DRAM latency under epilogue+barrier)
        float gnext[4];
        if (t < TT - 1) {
            const float* gr = g_gx + (size_t)(t + 1) * BB * GG
                              + (size_t)pb * GG + j0 + pjl;
#pragma unroll
            for (int g = 0; g < 4; g++) gnext[g] = gr[g * HH];
        }

        // stage partial D planes to SMEM (plane kh)
        {
            float* sgp = sg + kh * (64 * 36);
            int m = m0 + (l >> 2);
#pragma unroll
            for (int na = 0; na < 2; na++) {
                int n = n0 + na * 8 + 2 * (l & 3);
                *(float2*)&sgp[m * 36 + n]       = make_float2(acc[na][0], acc[na][1]);
                *(float2*)&sgp[(m + 8) * 36 + n] = make_float2(acc[na][2], acc[na][3]);
            }
        }
        __syncthreads();

        // pointwise LSTM cell: 1 elem/thread
        float* h_out = out + (size_t)t * BB * HH;
        __half* nh16 = g_h16[(t + 1) & 1];
        {
            const float* s0 = sg + pb * 36;
            const float* s1 = sg + 64 * 36 + pb * 36;
            float gi = s0[pjl]      + s1[pjl]      + gpre[0];
            float gf = s0[8 + pjl]  + s1[8 + pjl]  + gpre[1];
            float gg = s0[16 + pjl] + s1[16 + pjl] + gpre[2];
            float go = s0[24 + pjl] + s1[24 + pjl] + gpre[3];
            float ig = 1.0f / (1.0f + __expf(-gi));
            float fg = 1.0f / (1.0f + __expf(-gf));
            float gv = tanhf(gg);
            float og = 1.0f / (1.0f + __expf(-go));
            float cn = fg * c_reg + ig * gv;
            float hn = og * tanhf(cn);
            c_reg = cn;
            size_t hoff = (size_t)pb * HH + j0 + pjl;
            h_out[hoff] = hn;
            nh16[hoff] = __float2half(hn);
            if (t == TT - 1) {
                out[(size_t)TT * BB * HH + hoff] = hn;
                out[(size_t)TT * BB * HH + BB * HH + hoff] = cn;
            }
        }
#pragma unroll
        for (int g = 0; g < 4; g++) gpre[g] = gnext[g];

        // grid-wide barrier (monotonic release, replay-safe)
        if (t < TT - 1) {
            __threadfence();
            __syncthreads();
            if (tid == 0) {
                unsigned target = rel_base + (unsigned)(t + 1);
                unsigned old = atomicAdd(&g_arrive, 1);
                if (old == NCTA - 1) {
                    g_arrive = 0;
                    __threadfence();
                    *(volatile unsigned*)&g_release = target;
                }
            }
            {
                unsigned target = rel_base + (unsigned)(t + 1);
                if (l == 0) {
                    while ((int)(*(volatile unsigned*)&g_release - target) < 0) {}
                }
                __syncwarp();
                __threadfence();
            }
        }
    }
}

extern "C" void kernel_launch(void* const* d_in, const int* in_sizes, int n_in,
                              void* d_out, int out_size)
{
    const float* x    = (const float*)d_in[0];
    const float* h0   = (const float*)d_in[1];
    const float* c0   = (const float*)d_in[2];
    const float* w_ih = (const float*)d_in[3];
    const float* b_ih = (const float*)d_in[4];
    const float* w_hh = (const float*)d_in[5];
    const float* b_hh = (const float*)d_in[6];
    float* out = (float*)d_out;
    (void)in_sizes; (void)n_in; (void)out_size;

    // Prep
    prep_x_kernel<<<(int)(((size_t)TT * BB * DD + 255) / 256), 256>>>(x);
    prep_wih_kernel<<<(GG * DD + 255) / 256, 256>>>(w_ih);
    prep_whh_kernel<<<(GG * HH + 255) / 256, 256>>>(w_hh);
    prep_h_kernel<<<(BB * HH + 255) / 256, 256>>>(h0);

    // Phase 1: input projection on tensor cores (3-term bf16, fp32-exact-ish)
    cudaFuncSetAttribute(gemm_gx_mma,
                         cudaFuncAttributeMaxDynamicSharedMemorySize, P1_SMEM);
    dim3 g1(GG / 128, (TT * BB) / 128);
    gemm_gx_mma<<<g1, 256, P1_SMEM>>>(b_ih, b_hh);

    // Phase 2: persistent fp16 tensor-core recurrence
    cudaFuncSetAttribute(lstm_mma_kernel,
                         cudaFuncAttributeMaxDynamicSharedMemorySize, R_SMEM);
    lstm_mma_kernel<<<NCTA, 512, R_SMEM>>>(c0, out);
}